// round 14
// baseline (speedup 1.0000x reference)
#include <cuda_runtime.h>
#include <cuda_fp16.h>
#include <cstdint>

#define NHW 196
#define SPT 25088   // 128 * 196

// ---------------- scratch (no cudaMalloc allowed) ----------------
__device__ uint16_t g_xt[(size_t)SPT * 1024];   // x NHWC fp16
__device__ uint16_t g_o1[(size_t)SPT * 256];    // conv1 out (+b1b+b2a) fp16
__device__ uint16_t g_o2[(size_t)SPT * 256];    // conv2 out (+b2b+b3a) fp16
__device__ uint16_t g_w1[256 * 1024];           // fp16
__device__ uint16_t g_w2[256 * 2304];           // fp16 [co][tap*256+ci]
__device__ uint16_t g_w3[1024 * 256];           // fp16

// ---------------- helpers ----------------
__device__ __forceinline__ uint32_t smem_u32(const void* p) {
    uint32_t a;
    asm("{ .reg .u64 t; cvta.to.shared.u64 t, %1; cvt.u32.u64 %0, t; }"
        : "=r"(a) : "l"(p));
    return a;
}
__device__ __forceinline__ uint32_t packh2(float a, float b) {
    uint32_t d;
    asm("cvt.rn.f16x2.f32 %0, %1, %2;" : "=r"(d) : "f"(b), "f"(a));
    return d;
}
__device__ __forceinline__ void ldsm4(uint32_t& r0, uint32_t& r1,
                                      uint32_t& r2, uint32_t& r3, uint32_t a) {
    asm volatile("ldmatrix.sync.aligned.m8n8.x4.shared.b16 {%0,%1,%2,%3}, [%4];"
                 : "=r"(r0), "=r"(r1), "=r"(r2), "=r"(r3) : "r"(a));
}
__device__ __forceinline__ void mma16816(float* c, const uint32_t* a, const uint32_t* b) {
    asm volatile("mma.sync.aligned.m16n8k16.row.col.f32.f16.f16.f32 "
                 "{%0,%1,%2,%3}, {%4,%5,%6,%7}, {%8,%9}, {%0,%1,%2,%3};"
                 : "+f"(c[0]), "+f"(c[1]), "+f"(c[2]), "+f"(c[3])
                 : "r"(a[0]), "r"(a[1]), "r"(a[2]), "r"(a[3]), "r"(b[0]), "r"(b[1]));
}
__device__ __forceinline__ void cp16(uint32_t dst, const void* src) {
    asm volatile("cp.async.cg.shared.global [%0], [%1], 16;"
                 :: "r"(dst), "l"(src) : "memory");
}
__device__ __forceinline__ void cp16z(uint32_t dst, const void* src, int sz) {
    asm volatile("cp.async.cg.shared.global [%0], [%1], 16, %2;"
                 :: "r"(dst), "l"(src), "r"(sz) : "memory");
}
#define CP_COMMIT() asm volatile("cp.async.commit_group;" ::: "memory")
template <int N>
__device__ __forceinline__ void cp_wait() {
    asm volatile("cp.async.wait_group %0;" :: "n"(N) : "memory");
}

// ---------------- fused prologue ----------------
__global__ __launch_bounds__(256)
void prologue(const float* __restrict__ x, uint16_t* __restrict__ xt,
              const float2* __restrict__ w1, uint32_t* __restrict__ w1o,
              const float2* __restrict__ w3, uint32_t* __restrict__ w3o,
              const float* __restrict__ w2, uint16_t* __restrict__ w2o) {
    const int b = blockIdx.x;
    const int tid = threadIdx.x;
    if (b < 28672) {
        __shared__ float tile[32][33];
        const int hwt = b % 7;
        const int rest = b / 7;
        const int ct = rest & 31;
        const int n = rest >> 5;
        const int c0 = ct * 32, hw0 = hwt * 32;
        const int tx = tid & 31, ty = tid >> 5;
#pragma unroll
        for (int i = 0; i < 4; i++) {
            int hw = hw0 + tx;
            if (hw < NHW)
                tile[ty + 8 * i][tx] =
                    x[((size_t)n * 1024 + c0 + ty + 8 * i) * NHW + hw];
        }
        __syncthreads();
        const int cp = tid & 15;
        uint32_t* oh = (uint32_t*)xt;
#pragma unroll
        for (int i = 0; i < 2; i++) {
            int hwl = (tid >> 4) + 16 * i;
            int hw = hw0 + hwl;
            if (hw < NHW) {
                size_t o = (size_t)(n * NHW + hw) * 512 + (c0 >> 1) + cp;
                oh[o] = packh2(tile[2 * cp][hwl], tile[2 * cp + 1][hwl]);
            }
        }
    } else if (b < 29184) {
        const int i = (b - 28672) * 256 + tid;
        float2 v = w1[i];
        w1o[i] = packh2(v.x, v.y);
    } else if (b < 29696) {
        const int i = (b - 29184) * 256 + tid;
        float2 v = w3[i];
        w3o[i] = packh2(v.x, v.y);
    } else {
        const int i = (b - 29696) * 256 + tid;
        const int co = i / 2304, rem = i - co * 2304;
        const int tap = rem >> 8, ci = rem & 255;
        w2o[i] = __half_as_ushort(__float2half_rn(w2[co * 2304 + ci * 9 + tap]));
    }
}

// ---------------- SMEM: 4 stages x 15360B ----------------
// per stage: A (64 rows x 80B) @0, B (128 rows x 80B) @5120
static constexpr int STAGE = 15360;
static constexpr int NSTG = 4;
static constexpr int SMEM_BYTES = NSTG * STAGE;   // 61440 -> 3 CTAs/SM (smem)

// ---------------- main mma conv kernel (128 threads, 4 warps of 32x64) -----
// D[sp 64, co 128] = Act[sp,K] * W[co,K]^T (+ fused biases / residual)
template <int CONV>
__global__ __launch_bounds__(128, 3)
void conv_mma(const uint16_t* __restrict__ act, const uint16_t* __restrict__ wgt,
              void* __restrict__ out0, const float* __restrict__ xres,
              const float* __restrict__ pa, const float* __restrict__ pb,
              const float* __restrict__ pc) {
    constexpr int K   = (CONV == 1) ? 1024 : (CONV == 2) ? 2304 : 256;
    constexpr int NKB = K / 32;
    constexpr int NB  = (CONV == 3) ? 8 : 2;   // co tiles of 128

    extern __shared__ __align__(16) char smem[];
    const uint32_t sb = smem_u32(smem);
    const int tid  = threadIdx.x;
    const int lane = tid & 31, w = tid >> 5;
    const int wm = w >> 1, wn = w & 1;   // 2x2 warp grid, 32x64 tiles

    const int bid = blockIdx.x;
    const int mt_ = bid / NB;
    const int co0 = (bid - mt_ * NB) * 128;
    const int sp0 = mt_ * 64;

    // loader mapping: row r (0..63), chunk pair q2 (2 x 16B of 64B row)
    const int r  = tid >> 1;
    const int q2 = (tid & 1) * 2;
    int an = 0, ahh = 0, aww = 0;
    if (CONV == 2) {
        int sp = sp0 + r;
        an = sp / NHW;
        int rem = sp - an * NHW;
        ahh = rem / 14;
        aww = rem - ahh * 14;
    }

    auto issue = [&](int kb) {
        const int s = kb & (NSTG - 1);
        const uint32_t stg = sb + (uint32_t)s * STAGE;
        const uint32_t dst = stg + (uint32_t)r * 80 + (uint32_t)q2 * 16;
        if (CONV == 2) {
            const int tap = kb >> 3;
            const int dh = tap / 3 - 1, dw = tap - (tap / 3) * 3 - 1;
            const int hh = ahh + dh, ww = aww + dw;
            const bool ok = ((unsigned)hh < 14u) && ((unsigned)ww < 14u);
            const int sz = ok ? 16 : 0;
            const size_t off = ok
                ? ((size_t)(an * NHW + hh * 14 + ww)) * 256 + (kb & 7) * 32 + q2 * 8
                : 0;
            cp16z(dst, act + off, sz);
            cp16z(dst + 16, act + off + 8, sz);
        } else {
            const size_t off = (size_t)(sp0 + r) * K + kb * 32 + q2 * 8;
            cp16(dst, act + off);
            cp16(dst + 16, act + off + 8);
        }
        const uint32_t bb = stg + 5120;
#pragma unroll
        for (int j = 0; j < 2; j++) {
            const int rb = r + 64 * j;
            const size_t boff = (size_t)(co0 + rb) * K + kb * 32 + q2 * 8;
            const uint32_t bdst = bb + (uint32_t)rb * 80 + (uint32_t)q2 * 16;
            cp16(bdst, wgt + boff);
            cp16(bdst + 16, wgt + boff + 8);
        }
    };

    float acc[2][8][4];
#pragma unroll
    for (int i = 0; i < 2; i++)
#pragma unroll
        for (int j = 0; j < 8; j++)
#pragma unroll
            for (int p = 0; p < 4; p++) acc[i][j][p] = 0.f;

    const uint32_t a_off =
        (uint32_t)(wm * 32 + (lane & 15)) * 80 + (((uint32_t)lane >> 4) << 4);
    const uint32_t b_off =
        (uint32_t)(wn * 64 + ((lane >> 4) << 3) + (lane & 7)) * 80 +
        (((uint32_t)(lane >> 3) & 1u) << 4);

    auto compute = [&](int s) {
        const uint32_t st = sb + (uint32_t)s * STAGE;
#pragma unroll
        for (int ks = 0; ks < 2; ks++) {
            uint32_t A[2][4], B[4][4];
#pragma unroll
            for (int mt = 0; mt < 2; mt++) {
                uint32_t ad = st + a_off + mt * (16 * 80) + ks * 32;
                ldsm4(A[mt][0], A[mt][1], A[mt][2], A[mt][3], ad);
            }
#pragma unroll
            for (int np = 0; np < 4; np++) {
                uint32_t bd = st + 5120 + b_off + np * (16 * 80) + ks * 32;
                ldsm4(B[np][0], B[np][1], B[np][2], B[np][3], bd);
            }
#pragma unroll
            for (int mt = 0; mt < 2; mt++)
#pragma unroll
                for (int nt = 0; nt < 8; nt++)
                    mma16816(acc[mt][nt], A[mt], &B[nt >> 1][(nt & 1) << 1]);
        }
    };

    // ---- async pipeline (4 stages, 1 kb per barrier) ----
#pragma unroll
    for (int s = 0; s < NSTG - 1; s++) {
        if (s < NKB) issue(s);
        CP_COMMIT();
    }
    for (int kb = 0; kb < NKB; kb++) {
        cp_wait<NSTG - 2>();
        __syncthreads();
        const int nx = kb + NSTG - 1;
        if (nx < NKB) issue(nx);
        CP_COMMIT();
        compute(kb & (NSTG - 1));
    }

    // ---- epilogue ----
    const int g = lane >> 2, t2 = (lane & 3) * 2;
    if (CONV != 3) {
        const float ob = pa[0] + pb[0];
        uint32_t* oh = (uint32_t*)out0;
#pragma unroll
        for (int mt = 0; mt < 2; mt++) {
            const int row = sp0 + wm * 32 + mt * 16 + g;
#pragma unroll
            for (int nt = 0; nt < 8; nt++) {
                const int col = co0 + wn * 64 + nt * 8 + t2;
                size_t idx = (size_t)row * 128 + (col >> 1);
                oh[idx] = packh2(acc[mt][nt][0] + ob, acc[mt][nt][1] + ob);
                oh[idx + 8 * 128] = packh2(acc[mt][nt][2] + ob, acc[mt][nt][3] + ob);
            }
        }
    } else {
        const float ob = pa[0], rs = pb[0], rb = pc[0];
        float* out = (float*)out0;
        float* bn = (float*)smem;   // 64 x 133 fp32 bounce
        __syncthreads();
#pragma unroll
        for (int mt = 0; mt < 2; mt++) {
            const int row = wm * 32 + mt * 16 + g;
#pragma unroll
            for (int nt = 0; nt < 8; nt++) {
                const int col = wn * 64 + nt * 8 + t2;
                bn[row * 133 + col]           = fmaf(acc[mt][nt][0] + ob, rs, rb);
                bn[row * 133 + col + 1]       = fmaf(acc[mt][nt][1] + ob, rs, rb);
                bn[(row + 8) * 133 + col]     = fmaf(acc[mt][nt][2] + ob, rs, rb);
                bn[(row + 8) * 133 + col + 1] = fmaf(acc[mt][nt][3] + ob, rs, rb);
            }
        }
        __syncthreads();
        const int spl = tid & 63, coh = tid >> 6;   // coh 0..1
        const int sp = sp0 + spl;
        const int n2 = sp / NHW, hw2 = sp - n2 * NHW;
        const size_t base = ((size_t)n2 * 1024 + co0) * NHW + hw2;
        // batched residual: 16 outstanding LDGs per quarter (acc dead here)
#pragma unroll
        for (int half = 0; half < 4; half++) {
            float xv[16];
#pragma unroll
            for (int it = 0; it < 16; it++) {
                const int c = (half * 16 + it) * 2 + coh;
                xv[it] = xres[base + (size_t)c * NHW];
            }
#pragma unroll
            for (int it = 0; it < 16; it++) {
                const int c = (half * 16 + it) * 2 + coh;
                out[base + (size_t)c * NHW] =
                    fmaxf(bn[spl * 133 + c] + xv[it], 0.f);
            }
        }
    }
}

// ---------------- launch ----------------
extern "C" void kernel_launch(void* const* d_in, const int* in_sizes, int n_in,
                              void* d_out, int out_size) {
    const float* x   = (const float*)d_in[0];
    const float* w1  = (const float*)d_in[1];
    const float* w2  = (const float*)d_in[2];
    const float* w3  = (const float*)d_in[3];
    const float* b1b = (const float*)d_in[4];
    const float* b2a = (const float*)d_in[5];
    const float* b2b = (const float*)d_in[6];
    const float* b3a = (const float*)d_in[7];
    const float* b3b = (const float*)d_in[8];
    const float* rsc = (const float*)d_in[9];
    const float* rbi = (const float*)d_in[10];
    float* out = (float*)d_out;

    uint16_t *xt, *o1, *o2, *w1h, *w2h, *w3h;
    cudaGetSymbolAddress((void**)&xt, g_xt);
    cudaGetSymbolAddress((void**)&o1, g_o1);
    cudaGetSymbolAddress((void**)&o2, g_o2);
    cudaGetSymbolAddress((void**)&w1h, g_w1);
    cudaGetSymbolAddress((void**)&w2h, g_w2);
    cudaGetSymbolAddress((void**)&w3h, g_w3);

    cudaFuncSetAttribute(conv_mma<1>, cudaFuncAttributeMaxDynamicSharedMemorySize, SMEM_BYTES);
    cudaFuncSetAttribute(conv_mma<2>, cudaFuncAttributeMaxDynamicSharedMemorySize, SMEM_BYTES);
    cudaFuncSetAttribute(conv_mma<3>, cudaFuncAttributeMaxDynamicSharedMemorySize, SMEM_BYTES);

    // fused prologue: x transpose+cvt, w1/w3 cvt, w2 cvt+relayout — one launch
    prologue<<<32000, 256>>>(x, xt, (const float2*)w1, (uint32_t*)w1h,
                             (const float2*)w3, (uint32_t*)w3h, w2, w2h);

    // conv1: 1x1 1024->256; o1 = conv + b1b + b2a (NHWC fp16)
    conv_mma<1><<<784, 128, SMEM_BYTES>>>(xt, w1h, o1, nullptr, b1b, b2a, nullptr);
    // conv2: 3x3 pad1 256->256; o2 = conv + b2b + b3a (NHWC fp16)
    conv_mma<2><<<784, 128, SMEM_BYTES>>>(o1, w2h, o2, nullptr, b2b, b3a, nullptr);
    // conv3: 1x1 256->1024; out NCHW = relu((conv + b3b)*rs + rb + x)
    conv_mma<3><<<3136, 128, SMEM_BYTES>>>(o2, w3h, out, x, b3b, rsc, rbi);
}

// round 15
// speedup vs baseline: 1.1233x; 1.1233x over previous
#include <cuda_runtime.h>
#include <cuda_fp16.h>
#include <cstdint>

#define NHW 196
#define SPT 25088   // 128 * 196

// ---------------- scratch (no cudaMalloc allowed) ----------------
__device__ uint16_t g_xt[(size_t)SPT * 1024];   // x NHWC fp16
__device__ uint16_t g_o1[(size_t)SPT * 256];    // conv1 out (+b1b+b2a) fp16
__device__ uint16_t g_o2[(size_t)SPT * 256];    // conv2 out (+b2b+b3a) fp16
__device__ uint16_t g_w1[256 * 1024];           // fp16
__device__ uint16_t g_w2[256 * 2304];           // fp16 [co][tap*256+ci]
__device__ uint16_t g_w3[1024 * 256];           // fp16

// ---------------- helpers ----------------
__device__ __forceinline__ uint32_t smem_u32(const void* p) {
    uint32_t a;
    asm("{ .reg .u64 t; cvta.to.shared.u64 t, %1; cvt.u32.u64 %0, t; }"
        : "=r"(a) : "l"(p));
    return a;
}
__device__ __forceinline__ uint32_t packh2(float a, float b) {
    uint32_t d;
    asm("cvt.rn.f16x2.f32 %0, %1, %2;" : "=r"(d) : "f"(b), "f"(a));
    return d;
}
__device__ __forceinline__ void ldsm4(uint32_t& r0, uint32_t& r1,
                                      uint32_t& r2, uint32_t& r3, uint32_t a) {
    asm volatile("ldmatrix.sync.aligned.m8n8.x4.shared.b16 {%0,%1,%2,%3}, [%4];"
                 : "=r"(r0), "=r"(r1), "=r"(r2), "=r"(r3) : "r"(a));
}
__device__ __forceinline__ void mma16816(float* c, const uint32_t* a, const uint32_t* b) {
    asm volatile("mma.sync.aligned.m16n8k16.row.col.f32.f16.f16.f32 "
                 "{%0,%1,%2,%3}, {%4,%5,%6,%7}, {%8,%9}, {%0,%1,%2,%3};"
                 : "+f"(c[0]), "+f"(c[1]), "+f"(c[2]), "+f"(c[3])
                 : "r"(a[0]), "r"(a[1]), "r"(a[2]), "r"(a[3]), "r"(b[0]), "r"(b[1]));
}
__device__ __forceinline__ void cp16(uint32_t dst, const void* src) {
    asm volatile("cp.async.cg.shared.global [%0], [%1], 16;"
                 :: "r"(dst), "l"(src) : "memory");
}
__device__ __forceinline__ void cp16z(uint32_t dst, const void* src, int sz) {
    asm volatile("cp.async.cg.shared.global [%0], [%1], 16, %2;"
                 :: "r"(dst), "l"(src), "r"(sz) : "memory");
}
#define CP_COMMIT() asm volatile("cp.async.commit_group;" ::: "memory")
template <int N>
__device__ __forceinline__ void cp_wait() {
    asm volatile("cp.async.wait_group %0;" :: "n"(N) : "memory");
}

// ---------------- fused prologue ----------------
__global__ __launch_bounds__(256)
void prologue(const float* __restrict__ x, uint16_t* __restrict__ xt,
              const float2* __restrict__ w1, uint32_t* __restrict__ w1o,
              const float2* __restrict__ w3, uint32_t* __restrict__ w3o,
              const float* __restrict__ w2, uint16_t* __restrict__ w2o) {
    const int b = blockIdx.x;
    const int tid = threadIdx.x;
    if (b < 28672) {
        __shared__ float tile[32][33];
        const int hwt = b % 7;
        const int rest = b / 7;
        const int ct = rest & 31;
        const int n = rest >> 5;
        const int c0 = ct * 32, hw0 = hwt * 32;
        const int tx = tid & 31, ty = tid >> 5;
#pragma unroll
        for (int i = 0; i < 4; i++) {
            int hw = hw0 + tx;
            if (hw < NHW)
                tile[ty + 8 * i][tx] =
                    x[((size_t)n * 1024 + c0 + ty + 8 * i) * NHW + hw];
        }
        __syncthreads();
        const int cp = tid & 15;
        uint32_t* oh = (uint32_t*)xt;
#pragma unroll
        for (int i = 0; i < 2; i++) {
            int hwl = (tid >> 4) + 16 * i;
            int hw = hw0 + hwl;
            if (hw < NHW) {
                size_t o = (size_t)(n * NHW + hw) * 512 + (c0 >> 1) + cp;
                oh[o] = packh2(tile[2 * cp][hwl], tile[2 * cp + 1][hwl]);
            }
        }
    } else if (b < 29184) {
        const int i = (b - 28672) * 256 + tid;
        float2 v = w1[i];
        w1o[i] = packh2(v.x, v.y);
    } else if (b < 29696) {
        const int i = (b - 29184) * 256 + tid;
        float2 v = w3[i];
        w3o[i] = packh2(v.x, v.y);
    } else {
        const int i = (b - 29696) * 256 + tid;
        const int co = i / 2304, rem = i - co * 2304;
        const int tap = rem >> 8, ci = rem & 255;
        w2o[i] = __half_as_ushort(__float2half_rn(w2[co * 2304 + ci * 9 + tap]));
    }
}

// ---------------- per-conv geometry ----------------
// CONV 1/2: CTA 64x128, 8 warps (2m x 4n) of 32x32, 3 CTAs/SM  (R13 proven)
// CONV 3:   CTA 128x128, 8 warps (4m x 2n) of 32x64, 2 CTAs/SM (fat tiles)
template <int CONV> struct Cfg {
    static constexpr int K     = (CONV == 1) ? 1024 : (CONV == 2) ? 2304 : 256;
    static constexpr int MTILE = (CONV == 3) ? 128 : 64;       // sp rows per CTA
    static constexpr int NWN   = (CONV == 3) ? 8 : 4;          // n frags per warp
    static constexpr int NB    = (CONV == 3) ? 8 : 2;          // co tiles of 128
    static constexpr int STAGE = (CONV == 3) ? 20480 : 15360;  // A + B
    static constexpr int SMEM  = 4 * STAGE;
    static constexpr int MINB  = (CONV == 3) ? 2 : 3;
};

// ---------------- main mma conv kernel (256 threads, 8 warps) ----------------
// D[sp MTILE, co 128] = Act[sp,K] * W[co,K]^T (+ fused biases / residual)
template <int CONV>
__global__ __launch_bounds__(256, Cfg<CONV>::MINB)
void conv_mma(const uint16_t* __restrict__ act, const uint16_t* __restrict__ wgt,
              void* __restrict__ out0, const float* __restrict__ xres,
              const float* __restrict__ pa, const float* __restrict__ pb,
              const float* __restrict__ pc) {
    constexpr int K     = Cfg<CONV>::K;
    constexpr int NKB   = K / 32;
    constexpr int NB    = Cfg<CONV>::NB;
    constexpr int NWN   = Cfg<CONV>::NWN;
    constexpr int NBL   = NWN / 2;
    constexpr int MTILE = Cfg<CONV>::MTILE;
    constexpr int STAGE = Cfg<CONV>::STAGE;
    constexpr int BOFF  = MTILE * 80;   // B region offset within stage
    constexpr int NSTG  = 4;

    extern __shared__ __align__(16) char smem[];
    const uint32_t sb = smem_u32(smem);
    const int tid  = threadIdx.x;
    const int lane = tid & 31, w = tid >> 5;
    // warp grid: CONV3 4m x 2n; else 2m x 4n
    const int wm = (CONV == 3) ? (w >> 1) : (w >> 2);
    const int wn = (CONV == 3) ? (w & 1) : (w & 3);

    const int bid = blockIdx.x;
    const int mt_ = bid / NB;
    const int co0 = (bid - mt_ * NB) * 128;
    const int sp0 = mt_ * MTILE;

    // loader mapping
    const int r  = (CONV == 3) ? (tid >> 1) : (tid >> 2);      // A row
    const int q  = (CONV == 3) ? ((tid & 1) * 2) : (tid & 3);  // 16B chunk idx
    int an = 0, ahh = 0, aww = 0;
    if (CONV == 2) {
        int sp = sp0 + r;
        an = sp / NHW;
        int rem = sp - an * NHW;
        ahh = rem / 14;
        aww = rem - ahh * 14;
    }

    auto issue = [&](int kb) {
        const int s = kb & (NSTG - 1);
        const uint32_t stg = sb + (uint32_t)s * STAGE;
        const uint32_t dst = stg + (uint32_t)r * 80 + (uint32_t)q * 16;
        if (CONV == 2) {
            const int tap = kb >> 3;
            const int dh = tap / 3 - 1, dw = tap - (tap / 3) * 3 - 1;
            const int hh = ahh + dh, ww = aww + dw;
            const bool ok = ((unsigned)hh < 14u) && ((unsigned)ww < 14u);
            const int sz = ok ? 16 : 0;
            const size_t off = ok
                ? ((size_t)(an * NHW + hh * 14 + ww)) * 256 + (kb & 7) * 32 + q * 8
                : 0;
            cp16z(dst, act + off, sz);
        } else if (CONV == 1) {
            cp16(dst, act + (size_t)(sp0 + r) * K + kb * 32 + q * 8);
        } else {   // CONV 3: two chunks per thread
            const size_t off = (size_t)(sp0 + r) * K + kb * 32 + q * 8;
            cp16(dst, act + off);
            cp16(dst + 16, act + off + 8);
        }
        const uint32_t bb = stg + BOFF;
        if (CONV == 3) {
            const size_t boff = (size_t)(co0 + r) * K + kb * 32 + q * 8;
            const uint32_t bdst = bb + (uint32_t)r * 80 + (uint32_t)q * 16;
            cp16(bdst, wgt + boff);
            cp16(bdst + 16, wgt + boff + 8);
        } else {
#pragma unroll
            for (int j = 0; j < 2; j++) {
                const int rb = r + 64 * j;
                cp16(bb + (uint32_t)rb * 80 + (uint32_t)q * 16,
                     wgt + (size_t)(co0 + rb) * K + kb * 32 + q * 8);
            }
        }
    };

    float acc[2][NWN][4];
#pragma unroll
    for (int i = 0; i < 2; i++)
#pragma unroll
        for (int j = 0; j < NWN; j++)
#pragma unroll
            for (int p = 0; p < 4; p++) acc[i][j][p] = 0.f;

    const uint32_t a_off =
        (uint32_t)(wm * 32 + (lane & 15)) * 80 + (((uint32_t)lane >> 4) << 4);
    const uint32_t b_off =
        (uint32_t)(wn * (NWN * 8) + ((lane >> 4) << 3) + (lane & 7)) * 80 +
        (((uint32_t)(lane >> 3) & 1u) << 4);

    auto compute = [&](int s) {
        const uint32_t st = sb + (uint32_t)s * STAGE;
#pragma unroll
        for (int ks = 0; ks < 2; ks++) {
            uint32_t A[2][4], B[NBL][4];
#pragma unroll
            for (int mt = 0; mt < 2; mt++) {
                uint32_t ad = st + a_off + mt * (16 * 80) + ks * 32;
                ldsm4(A[mt][0], A[mt][1], A[mt][2], A[mt][3], ad);
            }
#pragma unroll
            for (int np = 0; np < NBL; np++) {
                uint32_t bd = st + BOFF + b_off + np * (16 * 80) + ks * 32;
                ldsm4(B[np][0], B[np][1], B[np][2], B[np][3], bd);
            }
#pragma unroll
            for (int mt = 0; mt < 2; mt++)
#pragma unroll
                for (int nt = 0; nt < NWN; nt++)
                    mma16816(acc[mt][nt], A[mt], &B[nt >> 1][(nt & 1) << 1]);
        }
    };

    // ---- async pipeline (4 stages, 1 kb per barrier) ----
#pragma unroll
    for (int s = 0; s < NSTG - 1; s++) {
        if (s < NKB) issue(s);
        CP_COMMIT();
    }
    for (int kb = 0; kb < NKB; kb++) {
        cp_wait<NSTG - 2>();
        __syncthreads();
        const int nx = kb + NSTG - 1;
        if (nx < NKB) issue(nx);
        CP_COMMIT();
        compute(kb & (NSTG - 1));
    }

    // ---- epilogue ----
    const int g = lane >> 2, t2 = (lane & 3) * 2;
    if (CONV != 3) {
        const float ob = pa[0] + pb[0];
        uint32_t* oh = (uint32_t*)out0;
#pragma unroll
        for (int mt = 0; mt < 2; mt++) {
            const int row = sp0 + wm * 32 + mt * 16 + g;
#pragma unroll
            for (int nt = 0; nt < NWN; nt++) {
                const int col = co0 + wn * (NWN * 8) + nt * 8 + t2;
                size_t idx = (size_t)row * 128 + (col >> 1);
                oh[idx] = packh2(acc[mt][nt][0] + ob, acc[mt][nt][1] + ob);
                oh[idx + 8 * 128] = packh2(acc[mt][nt][2] + ob, acc[mt][nt][3] + ob);
            }
        }
    } else {
        const float ob = pa[0], rs = pb[0], rb = pc[0];
        float* out = (float*)out0;
        float* bn = (float*)smem;   // 128 x 133 fp32 bounce (68KB <= 80KB)
        __syncthreads();
#pragma unroll
        for (int mt = 0; mt < 2; mt++) {
            const int row = wm * 32 + mt * 16 + g;
#pragma unroll
            for (int nt = 0; nt < NWN; nt++) {
                const int col = wn * (NWN * 8) + nt * 8 + t2;
                bn[row * 133 + col]           = fmaf(acc[mt][nt][0] + ob, rs, rb);
                bn[row * 133 + col + 1]       = fmaf(acc[mt][nt][1] + ob, rs, rb);
                bn[(row + 8) * 133 + col]     = fmaf(acc[mt][nt][2] + ob, rs, rb);
                bn[(row + 8) * 133 + col + 1] = fmaf(acc[mt][nt][3] + ob, rs, rb);
            }
        }
        __syncthreads();
        const int spl = tid & 127, coh = tid >> 7;   // coh 0..1
        const int sp = sp0 + spl;
        const int n2 = sp / NHW, hw2 = sp - n2 * NHW;
        const size_t base = ((size_t)n2 * 1024 + co0) * NHW + hw2;
        // batched residual: 16 outstanding LDGs per batch (acc dead here)
#pragma unroll
        for (int batch = 0; batch < 4; batch++) {
            float xv[16];
#pragma unroll
            for (int it = 0; it < 16; it++) {
                const int c = (batch * 16 + it) * 2 + coh;
                xv[it] = xres[base + (size_t)c * NHW];
            }
#pragma unroll
            for (int it = 0; it < 16; it++) {
                const int c = (batch * 16 + it) * 2 + coh;
                out[base + (size_t)c * NHW] =
                    fmaxf(bn[spl * 133 + c] + xv[it], 0.f);
            }
        }
    }
}

// ---------------- launch ----------------
extern "C" void kernel_launch(void* const* d_in, const int* in_sizes, int n_in,
                              void* d_out, int out_size) {
    const float* x   = (const float*)d_in[0];
    const float* w1  = (const float*)d_in[1];
    const float* w2  = (const float*)d_in[2];
    const float* w3  = (const float*)d_in[3];
    const float* b1b = (const float*)d_in[4];
    const float* b2a = (const float*)d_in[5];
    const float* b2b = (const float*)d_in[6];
    const float* b3a = (const float*)d_in[7];
    const float* b3b = (const float*)d_in[8];
    const float* rsc = (const float*)d_in[9];
    const float* rbi = (const float*)d_in[10];
    float* out = (float*)d_out;

    uint16_t *xt, *o1, *o2, *w1h, *w2h, *w3h;
    cudaGetSymbolAddress((void**)&xt, g_xt);
    cudaGetSymbolAddress((void**)&o1, g_o1);
    cudaGetSymbolAddress((void**)&o2, g_o2);
    cudaGetSymbolAddress((void**)&w1h, g_w1);
    cudaGetSymbolAddress((void**)&w2h, g_w2);
    cudaGetSymbolAddress((void**)&w3h, g_w3);

    cudaFuncSetAttribute(conv_mma<1>, cudaFuncAttributeMaxDynamicSharedMemorySize, Cfg<1>::SMEM);
    cudaFuncSetAttribute(conv_mma<2>, cudaFuncAttributeMaxDynamicSharedMemorySize, Cfg<2>::SMEM);
    cudaFuncSetAttribute(conv_mma<3>, cudaFuncAttributeMaxDynamicSharedMemorySize, Cfg<3>::SMEM);

    // fused prologue: x transpose+cvt, w1/w3 cvt, w2 cvt+relayout — one launch
    prologue<<<32000, 256>>>(x, xt, (const float2*)w1, (uint32_t*)w1h,
                             (const float2*)w3, (uint32_t*)w3h, w2, w2h);

    // conv1: 1x1 1024->256; o1 = conv + b1b + b2a (NHWC fp16)
    conv_mma<1><<<784, 256, Cfg<1>::SMEM>>>(xt, w1h, o1, nullptr, b1b, b2a, nullptr);
    // conv2: 3x3 pad1 256->256; o2 = conv + b2b + b3a (NHWC fp16)
    conv_mma<2><<<784, 256, Cfg<2>::SMEM>>>(o1, w2h, o2, nullptr, b2b, b3a, nullptr);
    // conv3: 1x1 256->1024 (CTA 128x128); out NCHW = relu((conv + b3b)*rs + rb + x)
    conv_mma<3><<<1568, 256, Cfg<3>::SMEM>>>(o2, w3h, out, x, b3b, rsc, rbi);
}